// round 11
// baseline (speedup 1.0000x reference)
#include <cuda_runtime.h>
#include <math_constants.h>

#define BD   64
#define MAXB 8192
#define MAXM 16384
#define TS   132   // smem row stride (floats) for transposed tiles

// ---------------- device scratch (static: no allocations allowed) ----------
__device__ float g_an[MAXB * BD];                    // normalized anchors
__device__ float g_cn[MAXM * BD];                    // normalized candidates (pos ++ neg)
__device__ float g_logits[(size_t)MAXB * MAXM];      // full sim matrix (512 MB)
__device__ float g_topv[MAXB * 32];
__device__ int   g_topi[MAXB * 32];

// ---------------- 1) normalize rows ------------------------------------------
// One THREAD per row. Replicates XLA:CPU + LLVM aarch64 lowering:
//   sum(x*x): HLO mul/add separately rounded (NO contract), reassoc allowed:
//   LoopVectorizer VF=4, IC=2 — UNFUSED chains:
//     acc0[l] = rn( acc0[l] + rn(x[8i+l]^2)   )   (i ascending)
//     acc1[l] = rn( acc1[l] + rn(x[8i+4+l]^2) )
//     t = acc0 + acc1                  (vector fadd)
//     s = (t0+t1) + (t2+t3)            (NEON faddp ladder)
//   den = max( sqrt.rn(s), 1e-8 )
//   divide -> multiply-by-reciprocal rewrite:
//     rcp = rn(1/den);  out_k = rn(x_k * rcp)
__global__ void normalize_kernel(const float* __restrict__ anchor,
                                 const float* __restrict__ pos,
                                 const float* __restrict__ neg,
                                 int B, int Nn) {
    int r = blockIdx.x * blockDim.x + threadIdx.x;
    int total = 2 * B + Nn;
    if (r >= total) return;

    const float* src;
    float* dst;
    if (r < B)            { src = anchor + (size_t)r * BD;         dst = g_an + (size_t)r * BD; }
    else if (r < 2 * B)   { src = pos    + (size_t)(r - B) * BD;   dst = g_cn + (size_t)(r - B) * BD; }
    else                  { src = neg    + (size_t)(r - 2*B) * BD; dst = g_cn + (size_t)(r - B) * BD; }

    float x[BD];
    #pragma unroll
    for (int k = 0; k < BD; ++k) x[k] = __ldg(src + k);

    float acc0[4] = {0.f, 0.f, 0.f, 0.f};
    float acc1[4] = {0.f, 0.f, 0.f, 0.f};
    #pragma unroll
    for (int i = 0; i < 8; ++i) {
        #pragma unroll
        for (int l = 0; l < 4; ++l)
            acc0[l] = __fadd_rn(acc0[l], __fmul_rn(x[8*i + l],     x[8*i + l]));     // UNFUSED
        #pragma unroll
        for (int l = 0; l < 4; ++l)
            acc1[l] = __fadd_rn(acc1[l], __fmul_rn(x[8*i + 4 + l], x[8*i + 4 + l])); // UNFUSED
    }
    float t0 = __fadd_rn(acc0[0], acc1[0]);
    float t1 = __fadd_rn(acc0[1], acc1[1]);
    float t2 = __fadd_rn(acc0[2], acc1[2]);
    float t3 = __fadd_rn(acc0[3], acc1[3]);
    float s  = __fadd_rn(__fadd_rn(t0, t1), __fadd_rn(t2, t3));   // faddp ladder

    float den = fmaxf(__fsqrt_rn(s), 1e-8f);
    float rcp = __fdiv_rn(1.0f, den);          // one rounded reciprocal
    #pragma unroll
    for (int k = 0; k < BD; ++k)
        dst[k] = __fmul_rn(x[k], rcp);         // multiply, NOT divide
}

// ---------------- 2) GEMM: logits = AN (8192x64) * CN^T (64x16384) ---------
// 128x128 tile per block, K=64 loaded once, 8x8/thread, k strictly sequential
// ascending with fused FMA per step (matches Eigen gebp single-accumulator).
__global__ void gemm_kernel(int M) {
    extern __shared__ float sm[];
    float* As = sm;                 // [64][TS] transposed: As[k*TS + m]
    float* Bs = sm + 64 * TS;       // [64][TS] transposed: Bs[k*TS + n]

    int t = threadIdx.x;            // 256 threads
    int rowBase = blockIdx.y * 128;
    int colBase = blockIdx.x * 128;

    {
        const float4* A4 = reinterpret_cast<const float4*>(g_an + (size_t)rowBase * BD);
        const float4* B4 = reinterpret_cast<const float4*>(g_cn + (size_t)colBase * BD);
        #pragma unroll
        for (int it = 0; it < 8; ++it) {
            int lin = it * 256 + t;     // 0..2047 float4 slots
            int r   = lin >> 4;         // 0..127 (tile row)
            int kq  = lin & 15;         // float4 index along K
            float4 va = A4[r * 16 + kq];
            float4 vb = B4[r * 16 + kq];
            int k = kq * 4;
            As[(k+0)*TS + r] = va.x; As[(k+1)*TS + r] = va.y;
            As[(k+2)*TS + r] = va.z; As[(k+3)*TS + r] = va.w;
            Bs[(k+0)*TS + r] = vb.x; Bs[(k+1)*TS + r] = vb.y;
            Bs[(k+2)*TS + r] = vb.z; Bs[(k+3)*TS + r] = vb.w;
        }
    }
    __syncthreads();

    int tx = t & 15, ty = t >> 4;
    int r0 = ty * 8, c0 = tx * 8;

    float acc[8][8];
    #pragma unroll
    for (int i = 0; i < 8; ++i)
        #pragma unroll
        for (int j = 0; j < 8; ++j)
            acc[i][j] = 0.f;

    #pragma unroll 8
    for (int k = 0; k < 64; ++k) {
        float4 a0 = *reinterpret_cast<const float4*>(&As[k*TS + r0]);
        float4 a1 = *reinterpret_cast<const float4*>(&As[k*TS + r0 + 4]);
        float4 b0 = *reinterpret_cast<const float4*>(&Bs[k*TS + c0]);
        float4 b1 = *reinterpret_cast<const float4*>(&Bs[k*TS + c0 + 4]);
        float a[8] = {a0.x,a0.y,a0.z,a0.w,a1.x,a1.y,a1.z,a1.w};
        float b[8] = {b0.x,b0.y,b0.z,b0.w,b1.x,b1.y,b1.z,b1.w};
        #pragma unroll
        for (int i = 0; i < 8; ++i)
            #pragma unroll
            for (int j = 0; j < 8; ++j)
                acc[i][j] = __fmaf_rn(a[i], b[j], acc[i][j]);   // fused, k-ascending
    }

    #pragma unroll
    for (int i = 0; i < 8; ++i) {
        float* Cp = g_logits + (size_t)(rowBase + r0 + i) * M + colBase + c0;
        reinterpret_cast<float4*>(Cp)[0] = make_float4(acc[i][0], acc[i][1], acc[i][2], acc[i][3]);
        reinterpret_cast<float4*>(Cp)[1] = make_float4(acc[i][4], acc[i][5], acc[i][6], acc[i][7]);
    }
}

// ---------------- 3) exact per-row top-32 of masked logits (warp per row) --
// Mask: v < diag, where diag = logits[row][row] (same array -> exact semantics).
// Tie-break: larger value first, then lower index (jax.lax.top_k semantics).
__global__ void topk_kernel(int B, int M) {
    int w    = (blockIdx.x * blockDim.x + threadIdx.x) >> 5;
    int lane = threadIdx.x & 31;
    if (w >= B) return;

    const float* __restrict__ Lrow = g_logits + (size_t)w * M;
    float d = Lrow[w];
    int iters = M >> 5;

    // pass 1: T = warp-min of per-lane masked maxima (>=32 masked values >= T)
    float mmax = -CUDART_INF_F;
    for (int i = 0; i < iters; ++i) {
        float v = Lrow[i * 32 + lane];
        if (v < d) mmax = fmaxf(mmax, v);
    }
    float T = mmax;
    #pragma unroll
    for (int off = 16; off; off >>= 1)
        T = fminf(T, __shfl_xor_sync(0xffffffffu, T, off));

    // pass 2: per-lane top-32 list over survivors (v<d && v>=T)
    float lv[32]; int li[32];
    #pragma unroll
    for (int k = 0; k < 32; ++k) { lv[k] = -CUDART_INF_F; li[k] = 0x7FFFFFFF; }
    float curmin = -CUDART_INF_F; int minslot = 0;

    for (int i = 0; i < iters; ++i) {
        int   j = i * 32 + lane;
        float v = Lrow[j];
        if (v < d && v >= T && v > curmin) {   // v==curmin: existing entry has lower index -> keep it
            lv[minslot] = v; li[minslot] = j;
            float mv = lv[0]; int mi = li[0]; int ms = 0;
            #pragma unroll
            for (int k = 1; k < 32; ++k) {
                // evict smallest value; among equal minima evict the HIGHEST index
                if (lv[k] < mv || (lv[k] == mv && li[k] > mi)) { mv = lv[k]; mi = li[k]; ms = k; }
            }
            curmin = mv; minslot = ms;
        }
    }

    // merge: 32 exact warp-argmax iterations
    float bv = lv[0]; int bi = li[0]; int bslot = 0;
    #pragma unroll
    for (int k = 1; k < 32; ++k)
        if (lv[k] > bv || (lv[k] == bv && li[k] < bi)) { bv = lv[k]; bi = li[k]; bslot = k; }

    for (int it = 0; it < 32; ++it) {
        float v = bv; int idx = bi;
        #pragma unroll
        for (int off = 16; off; off >>= 1) {
            float ov = __shfl_xor_sync(0xffffffffu, v,   off);
            int   oi = __shfl_xor_sync(0xffffffffu, idx, off);
            if (ov > v || (ov == v && oi < idx)) { v = ov; idx = oi; }
        }
        if (lane == 0) {
            bool valid = (idx != 0x7FFFFFFF);
            g_topi[w * 32 + it] = valid ? idx : -1;
            g_topv[w * 32 + it] = valid ? v : 0.f;
        }
        if (idx == bi && idx != 0x7FFFFFFF) {   // unique winner lane removes & rescans
            lv[bslot] = -CUDART_INF_F; li[bslot] = 0x7FFFFFFF;
            bv = lv[0]; bi = li[0]; bslot = 0;
            #pragma unroll
            for (int k = 1; k < 32; ++k)
                if (lv[k] > bv || (lv[k] == bv && li[k] < bi)) { bv = lv[k]; bi = li[k]; bslot = k; }
        }
    }
}

// ---------------- 4) zero-fill output, 5) scatter mined entries ------------
__global__ void fill_kernel(float4* __restrict__ out, size_t n4) {
    size_t i = (size_t)blockIdx.x * blockDim.x + threadIdx.x;
    if (i < n4) out[i] = make_float4(0.f, 0.f, 0.f, 0.f);
}

__global__ void scatter_kernel(float* __restrict__ out, int B, int M) {
    int idx = blockIdx.x * blockDim.x + threadIdx.x;
    if (idx >= B * 32) return;
    int row = idx >> 5;
    int j   = g_topi[idx];
    if (j >= 0) out[(size_t)row * M + j] = g_topv[idx];
}

// ---------------- launcher ---------------------------------------------------
extern "C" void kernel_launch(void* const* d_in, const int* in_sizes, int n_in,
                              void* d_out, int out_size) {
    const float* anchor = (const float*)d_in[0];
    const float* pos    = (const float*)d_in[1];
    const float* neg    = (const float*)d_in[2];
    float* out = (float*)d_out;

    int B  = in_sizes[0] / BD;   // 8192
    int Nn = in_sizes[2] / BD;   // 8192
    int M  = B + Nn;             // 16384

    // 1) normalize (thread per row, VF4/IC2 UNFUSED + faddp ladder + recip-mul)
    int totalRows = 2 * B + Nn;
    normalize_kernel<<<(totalRows + 127) / 128, 128>>>(anchor, pos, neg, B, Nn);

    // 2) GEMM -> g_logits
    int smemBytes = 2 * 64 * TS * (int)sizeof(float);   // 67584
    cudaFuncSetAttribute(gemm_kernel, cudaFuncAttributeMaxDynamicSharedMemorySize, smemBytes);
    dim3 ggrid(M / 128, B / 128);
    gemm_kernel<<<ggrid, 256, smemBytes>>>(M);

    // 3) exact top-32 per row (warp per row)
    topk_kernel<<<(B * 32 + 255) / 256, 256>>>(B, M);

    // 4) zero-fill output
    size_t n4 = ((size_t)B * M) / 4;
    fill_kernel<<<(unsigned)((n4 + 255) / 256), 256>>>((float4*)out, n4);

    // 5) scatter mined (value, index) pairs
    scatter_kernel<<<(B * 32 + 255) / 256, 256>>>(out, B, M);
}